// round 12
// baseline (speedup 1.0000x reference)
#include <cuda_runtime.h>
#include <cuda_bf16.h>
#include <cstdint>

#define D      1024
#define NTOK   2048
#define VOCAB  50257
#define VPAD   50304
#define NLAYER 12
#define NBLK   16

#define BM 128
#define BM_L 64
#define BN 64
#define BK 32

#define L_ARR 5120
#define L_BUF 25600          // AH AM AL B0 B1 (64x40 bf16 each)
#define L_NBUF 2
#define L_SS   (2 * L_NBUF * 0 + 2 * L_BUF)   // scale stage offset
#define F_BUF 30720          // AH AM (128x40) + BH BL (64x40)
#define F_NBUF 3

// ---------------- scratch ----------------
__device__ float g_xbuf[2][NTOK * D];
__device__ float g_p[NTOK];
__device__ __nv_bfloat16 g_xs[2][3][NTOK * D];
__device__ __nv_bfloat16 g_wb[(size_t)NLAYER * 2 * D * D];
__device__ __nv_bfloat16 g_wp2[2][(size_t)VPAD * D];

// ---------------------------------------------------------------- helpers

__device__ __forceinline__ void mma16816(float* c, const uint32_t* a, const uint32_t* b) {
    asm volatile(
        "mma.sync.aligned.m16n8k16.row.col.f32.bf16.bf16.f32 "
        "{%0,%1,%2,%3}, {%4,%5,%6,%7}, {%8,%9}, {%0,%1,%2,%3};"
        : "+f"(c[0]), "+f"(c[1]), "+f"(c[2]), "+f"(c[3])
        : "r"(a[0]), "r"(a[1]), "r"(a[2]), "r"(a[3]), "r"(b[0]), "r"(b[1]));
}

// d = a*b (no accumulate) — avoids zeroing movs
__device__ __forceinline__ void mma16816_z(float* c, const uint32_t* a, const uint32_t* b) {
    asm volatile(
        "mma.sync.aligned.m16n8k16.row.col.f32.bf16.bf16.f32 "
        "{%0,%1,%2,%3}, {%4,%5,%6,%7}, {%8,%9}, {%10,%11,%12,%13};"
        : "=f"(c[0]), "=f"(c[1]), "=f"(c[2]), "=f"(c[3])
        : "r"(a[0]), "r"(a[1]), "r"(a[2]), "r"(a[3]), "r"(b[0]), "r"(b[1]),
          "f"(0.f), "f"(0.f), "f"(0.f), "f"(0.f));
}

__device__ __forceinline__ uint32_t smem_u32(const void* p) {
    uint32_t a;
    asm("{ .reg .u64 t; cvta.to.shared.u64 t, %1; cvt.u32.u64 %0, t; }" : "=r"(a) : "l"(p));
    return a;
}

__device__ __forceinline__ void ldsm_x4(uint32_t& r0, uint32_t& r1, uint32_t& r2, uint32_t& r3,
                                        uint32_t addr) {
    asm volatile("ldmatrix.sync.aligned.m8n8.x4.shared.b16 {%0,%1,%2,%3}, [%4];"
                 : "=r"(r0), "=r"(r1), "=r"(r2), "=r"(r3) : "r"(addr));
}

__device__ __forceinline__ void cpa16(uint32_t smaddr, const void* g) {
    asm volatile("cp.async.ca.shared.global [%0], [%1], 16;" :: "r"(smaddr), "l"(g) : "memory");
}
#define CP_COMMIT() asm volatile("cp.async.commit_group;" ::: "memory")
#define CP_WAIT1()  asm volatile("cp.async.wait_group 1;" ::: "memory")
#define CP_WAIT0()  asm volatile("cp.async.wait_group 0;" ::: "memory")

__device__ __forceinline__ void split3(float x, __nv_bfloat16& h, __nv_bfloat16& m, __nv_bfloat16& l) {
    h = __float2bfloat16(x);
    float r1 = x - __bfloat162float(h);
    m = __float2bfloat16(r1);
    float r2 = r1 - __bfloat162float(m);
    l = __float2bfloat16(r2);
}

__device__ __forceinline__ void split2(float x, __nv_bfloat16& h, __nv_bfloat16& l) {
    h = __float2bfloat16(x);
    l = __float2bfloat16(x - __bfloat162float(h));
}

__device__ __forceinline__ uint32_t pack_bf2(__nv_bfloat16 a, __nv_bfloat16 b) {
    __nv_bfloat162 t(a, b);
    return *reinterpret_cast<uint32_t*>(&t);
}

// ---------------------------------------------------------------- pre-convert

__global__ void conv_w_kernel(const float* __restrict__ w0, const float* __restrict__ w1) {
    size_t t = (size_t)blockIdx.x * 256 + threadIdx.x;
    size_t e = t * 4;
    int l = (int)(e >> 20);
    size_t off = e & 1048575;
    float4 v0 = *reinterpret_cast<const float4*>(w0 + e);
    float4 v1 = *reinterpret_cast<const float4*>(w1 + e);
    uint2 p0, p1;
    p0.x = pack_bf2(__float2bfloat16(v0.x), __float2bfloat16(v0.y));
    p0.y = pack_bf2(__float2bfloat16(v0.z), __float2bfloat16(v0.w));
    p1.x = pack_bf2(__float2bfloat16(v1.x), __float2bfloat16(v1.y));
    p1.y = pack_bf2(__float2bfloat16(v1.z), __float2bfloat16(v1.w));
    __nv_bfloat16* d0 = g_wb + (size_t)l * 2097152 + off;
    *reinterpret_cast<uint2*>(d0) = p0;
    *reinterpret_cast<uint2*>(d0 + 1048576) = p1;
}

__global__ void conv_wp_kernel(const float* __restrict__ wp) {
    size_t t = (size_t)blockIdx.x * 256 + threadIdx.x;
    size_t e = t * 4;
    size_t row = e >> 10;
    float4 v = make_float4(0.f, 0.f, 0.f, 0.f);
    if (row < VOCAB) v = *reinterpret_cast<const float4*>(wp + e);
    __nv_bfloat16 h0, l0, h1, l1, h2, l2, h3, l3;
    split2(v.x, h0, l0); split2(v.y, h1, l1); split2(v.z, h2, l2); split2(v.w, h3, l3);
    uint2 ph, pl;
    ph.x = pack_bf2(h0, h1); ph.y = pack_bf2(h2, h3);
    pl.x = pack_bf2(l0, l1); pl.y = pack_bf2(l2, l3);
    *reinterpret_cast<uint2*>(&g_wp2[0][e]) = ph;
    *reinterpret_cast<uint2*>(&g_wp2[1][e]) = pl;
}

// ---------------------------------------------------------------- embed / router

__global__ void embed_kernel(const int* __restrict__ ids, const float* __restrict__ emb) {
    int n = blockIdx.x;
    int tid = threadIdx.x;
    int id = ids[n];
    float4 v = reinterpret_cast<const float4*>(emb + (size_t)id * D)[tid];
    reinterpret_cast<float4*>(&g_xbuf[0][(size_t)n * D])[tid] = v;
    __nv_bfloat16 h0, m0, l0, h1, m1, l1, h2, m2, l2, h3, m3, l3;
    split3(v.x, h0, m0, l0); split3(v.y, h1, m1, l1);
    split3(v.z, h2, m2, l2); split3(v.w, h3, m3, l3);
    size_t e = (size_t)n * D + tid * 4;
    uint2 p;
    p.x = pack_bf2(h0, h1); p.y = pack_bf2(h2, h3);
    *reinterpret_cast<uint2*>(&g_xs[0][0][e]) = p;
    p.x = pack_bf2(m0, m1); p.y = pack_bf2(m2, m3);
    *reinterpret_cast<uint2*>(&g_xs[0][1][e]) = p;
    p.x = pack_bf2(l0, l1); p.y = pack_bf2(l2, l3);
    *reinterpret_cast<uint2*>(&g_xs[0][2][e]) = p;
}

__global__ __launch_bounds__(256) void router_kernel(
    int par, const float* __restrict__ rw,
    const float* __restrict__ rb, float* __restrict__ probs_out)
{
    int warp = threadIdx.x >> 5, lane = threadIdx.x & 31;
    int n = blockIdx.x * 8 + warp;
    const float4* x = reinterpret_cast<const float4*>(&g_xbuf[par][(size_t)n * D]);
    const float4* w = reinterpret_cast<const float4*>(rw);
    float s = 0.f;
#pragma unroll
    for (int i = 0; i < 8; i++) {
        float4 xv = x[i * 32 + lane];
        float4 wv = __ldg(&w[i * 32 + lane]);
        s += xv.x * wv.x + xv.y * wv.y + xv.z * wv.z + xv.w * wv.w;
    }
#pragma unroll
    for (int off = 16; off > 0; off >>= 1)
        s += __shfl_xor_sync(0xFFFFFFFF, s, off);
    if (lane == 0) {
        float p = 1.f / (1.f + expf(-(s + rb[0])));
        g_p[n] = p;
        probs_out[n] = p;
    }
}

// ---------------------------------------------------------------- per-layer dual GEMM
// Single shared c accumulator: per ks-step do branch0 MMAs -> fold -> branch1 MMAs -> fold.
// Scales staged in smem. ~80 regs -> 3 CTAs/SM.

__global__ __launch_bounds__(256, 3) void layer_gemm_kernel(
    int par, int l,
    const float* __restrict__ s0, const float* __restrict__ s1)
{
    extern __shared__ char sm[];
    const float* x_in  = g_xbuf[par];
    float*       x_out = g_xbuf[par ^ 1];
    const __nv_bfloat16* xsH = g_xs[par][0];
    const __nv_bfloat16* xsM = g_xs[par][1];
    const __nv_bfloat16* xsL = g_xs[par][2];
    const __nv_bfloat16* wb = g_wb + (size_t)l * 2097152;

    uint32_t smb = smem_u32(sm);
    float* ss0 = reinterpret_cast<float*>(sm + 2 * L_BUF);   // [16][64]
    float* ss1 = ss0 + 1024;
    int tid = threadIdx.x;
    int lane = tid & 31, warp = tid >> 5;
    int wm = warp >> 1, wn = warp & 1;
    int g = lane >> 2, tg = lane & 3;
    int lrow = lane & 7, sel = lane >> 3;
    int m0 = blockIdx.y * BM_L;
    int n0 = blockIdx.x * BN;
    int rr = tid >> 2, c4 = tid & 3;

    // stage scales: ss[kb][col]
    for (int e = tid; e < 1024; e += 256) {
        int kb = e >> 6, col = e & 63;
        ss0[e] = __ldg(&s0[(size_t)(n0 + col) * NBLK + kb]);
        ss1[e] = __ldg(&s1[(size_t)(n0 + col) * NBLK + kb]);
    }

    float p0r = g_p[m0 + wm * 16 + g];
    float p1r = g_p[m0 + wm * 16 + g + 8];

    float acc0T[4][4], acc1T[4][4];
#pragma unroll
    for (int j = 0; j < 4; j++)
#pragma unroll
        for (int q = 0; q < 4; q++) { acc0T[j][q] = 0.f; acc1T[j][q] = 0.f; }

    auto load_tile = [&](int buf, int k0) {
        uint32_t dstb = smb + buf * L_BUF + rr * 80 + c4 * 16;
        size_t asrc = (size_t)(m0 + rr) * D + k0 + c4 * 8;
        size_t bsrc = (size_t)(n0 + rr) * D + k0 + c4 * 8;
        cpa16(dstb,             xsH + asrc);
        cpa16(dstb + 1 * L_ARR, xsM + asrc);
        cpa16(dstb + 2 * L_ARR, xsL + asrc);
        cpa16(dstb + 3 * L_ARR, wb + bsrc);
        cpa16(dstb + 4 * L_ARR, wb + 1048576 + bsrc);
    };

    load_tile(0, 0); CP_COMMIT();

    for (int ktg = 0; ktg < 32; ktg++) {
        int buf = ktg & 1;
        CP_WAIT0();
        __syncthreads();            // buf ready for all; prior reads of buf^1 done
        if (ktg + 1 < 32) { load_tile(buf ^ 1, (ktg + 1) * BK); CP_COMMIT(); }

        int kb = ktg >> 1;
        const float* ssk0 = ss0 + kb * 64;
        const float* ssk1 = ss1 + kb * 64;
        uint32_t bb = smb + buf * L_BUF;

#pragma unroll
        for (int ks = 0; ks < BK; ks += 16) {
            uint32_t aoff = (uint32_t)((wm * 16 + lrow + (sel & 1) * 8) * 80 + (ks + (sel >> 1) * 8) * 2);
            uint32_t aH[4], aM[4], aL[4];
            ldsm_x4(aH[0], aH[1], aH[2], aH[3], bb + aoff);
            ldsm_x4(aM[0], aM[1], aM[2], aM[3], bb + 1 * L_ARR + aoff);
            ldsm_x4(aL[0], aL[1], aL[2], aL[3], bb + 2 * L_ARR + aoff);

            uint32_t b[4][2];
            float c[4][4];
            // ---- branch 0 ----
#pragma unroll
            for (int p2 = 0; p2 < 2; p2++) {
                uint32_t boff = (uint32_t)((wn * 32 + p2 * 16 + lrow + (sel >> 1) * 8) * 80 + (ks + (sel & 1) * 8) * 2);
                ldsm_x4(b[p2*2][0], b[p2*2][1], b[p2*2+1][0], b[p2*2+1][1], bb + 3 * L_ARR + boff);
            }
#pragma unroll
            for (int nt = 0; nt < 4; nt++) {
                mma16816_z(c[nt], aH, b[nt]);
                mma16816(c[nt], aM, b[nt]);
                mma16816(c[nt], aL, b[nt]);
            }
#pragma unroll
            for (int nt = 0; nt < 4; nt++) {
                int cl = wn * 32 + nt * 8 + tg * 2;
                float2 sv = *reinterpret_cast<const float2*>(ssk0 + cl);
                acc0T[nt][0] += sv.x * c[nt][0]; acc0T[nt][1] += sv.y * c[nt][1];
                acc0T[nt][2] += sv.x * c[nt][2]; acc0T[nt][3] += sv.y * c[nt][3];
            }
            // ---- branch 1 ----
#pragma unroll
            for (int p2 = 0; p2 < 2; p2++) {
                uint32_t boff = (uint32_t)((wn * 32 + p2 * 16 + lrow + (sel >> 1) * 8) * 80 + (ks + (sel & 1) * 8) * 2);
                ldsm_x4(b[p2*2][0], b[p2*2][1], b[p2*2+1][0], b[p2*2+1][1], bb + 4 * L_ARR + boff);
            }
#pragma unroll
            for (int nt = 0; nt < 4; nt++) {
                mma16816_z(c[nt], aH, b[nt]);
                mma16816(c[nt], aM, b[nt]);
                mma16816(c[nt], aL, b[nt]);
            }
#pragma unroll
            for (int nt = 0; nt < 4; nt++) {
                int cl = wn * 32 + nt * 8 + tg * 2;
                float2 sv = *reinterpret_cast<const float2*>(ssk1 + cl);
                acc1T[nt][0] += sv.x * c[nt][0]; acc1T[nt][1] += sv.y * c[nt][1];
                acc1T[nt][2] += sv.x * c[nt][2]; acc1T[nt][3] += sv.y * c[nt][3];
            }
        }
        __syncthreads();            // reads of buf done before next iter's loads overwrite it
    }

    // epilogue: x_out = x_in + (1-p)*acc0 + p*acc1; write 3-way splits
    {
        __nv_bfloat16* oH = g_xs[par ^ 1][0];
        __nv_bfloat16* oM = g_xs[par ^ 1][1];
        __nv_bfloat16* oL = g_xs[par ^ 1][2];
        int r = m0 + wm * 16 + g;
        float w0a = 1.f - p0r, w0b = 1.f - p1r;
#pragma unroll
        for (int nt = 0; nt < 4; nt++) {
            int cidx = n0 + wn * 32 + nt * 8 + tg * 2;
            size_t idx[4] = { (size_t)r * D + cidx, (size_t)r * D + cidx + 1,
                              (size_t)(r + 8) * D + cidx, (size_t)(r + 8) * D + cidx + 1 };
            float vals[4];
            vals[0] = x_in[idx[0]] + w0a * acc0T[nt][0] + p0r * acc1T[nt][0];
            vals[1] = x_in[idx[1]] + w0a * acc0T[nt][1] + p0r * acc1T[nt][1];
            vals[2] = x_in[idx[2]] + w0b * acc0T[nt][2] + p1r * acc1T[nt][2];
            vals[3] = x_in[idx[3]] + w0b * acc0T[nt][3] + p1r * acc1T[nt][3];
#pragma unroll
            for (int q = 0; q < 4; q++) {
                x_out[idx[q]] = vals[q];
                __nv_bfloat16 h, m, l2;
                split3(vals[q], h, m, l2);
                oH[idx[q]] = h; oM[idx[q]] = m; oL[idx[q]] = l2;
            }
        }
    }
}

// ---------------------------------------------------------------- output projection
// 512 threads, warp tile 16x32 (8m x 2n warps). 3 products: hH + hL + mH.
// 3-buffer cp.async, 2-ahead, wait->sync->issue ordering.

__global__ __launch_bounds__(512, 2) void final_gemm_kernel(float* __restrict__ out) {
    extern __shared__ char sm[];
    const __nv_bfloat16* xH = g_xs[0][0];
    const __nv_bfloat16* xM = g_xs[0][1];
    const __nv_bfloat16* wH = g_wp2[0];
    const __nv_bfloat16* wL = g_wp2[1];

    uint32_t smb = smem_u32(sm);
    int tid = threadIdx.x;
    int lane = tid & 31, warp = tid >> 5;
    int wm = warp >> 1, wn = warp & 1;          // 8m x 2n
    int g = lane >> 2, tg = lane & 3;
    int lrow = lane & 7, sel = lane >> 3;
    int m0 = blockIdx.x * BM;
    int n0 = blockIdx.y * BN;

    float acc[4][4];
#pragma unroll
    for (int j = 0; j < 4; j++)
#pragma unroll
        for (int q = 0; q < 4; q++) acc[j][q] = 0.f;

    int rr = tid >> 2, c4 = tid & 3;            // A loader: 128 rows x 4 chunks
    int t2 = tid & 255;
    int rb = t2 >> 2, cb = t2 & 3;              // B loader: 64 rows x 4 chunks, 2 arrays

    auto load_tile = [&](int buf, int k0) {
        uint32_t dstb = smb + buf * F_BUF;
        size_t a0 = (size_t)(m0 + rr) * D + k0 + c4 * 8;
        cpa16(dstb + rr * 80 + c4 * 16,         xH + a0);
        cpa16(dstb + 10240 + rr * 80 + c4 * 16, xM + a0);
        size_t bsrc = (size_t)(n0 + rb) * D + k0 + cb * 8;
        if (tid < 256) cpa16(dstb + 20480 + rb * 80 + cb * 16, wH + bsrc);
        else           cpa16(dstb + 25600 + rb * 80 + cb * 16, wL + bsrc);
    };

    load_tile(0, 0); CP_COMMIT();
    load_tile(1, BK); CP_COMMIT();

    for (int kt = 0; kt < 32; kt++) {
        int buf = kt % 3;
        if (kt < 31) CP_WAIT1(); else CP_WAIT0();
        __syncthreads();
        if (kt + 2 < 32) {
            int nb = buf + 2; if (nb >= 3) nb -= 3;
            load_tile(nb, (kt + 2) * BK); CP_COMMIT();
        }

        uint32_t bb = smb + buf * F_BUF;
#pragma unroll
        for (int ks = 0; ks < BK; ks += 16) {
            uint32_t aoff = (uint32_t)((wm * 16 + lrow + (sel & 1) * 8) * 80 + (ks + (sel >> 1) * 8) * 2);
            uint32_t aH[4], aM[4];
            ldsm_x4(aH[0], aH[1], aH[2], aH[3], bb + aoff);
            ldsm_x4(aM[0], aM[1], aM[2], aM[3], bb + 10240 + aoff);
            uint32_t bH[4][2], bL[4][2];
#pragma unroll
            for (int p2 = 0; p2 < 2; p2++) {
                uint32_t boff = (uint32_t)((wn * 32 + p2 * 16 + lrow + (sel >> 1) * 8) * 80 + (ks + (sel & 1) * 8) * 2);
                ldsm_x4(bH[p2*2][0], bH[p2*2][1], bH[p2*2+1][0], bH[p2*2+1][1], bb + 20480 + boff);
                ldsm_x4(bL[p2*2][0], bL[p2*2][1], bL[p2*2+1][0], bL[p2*2+1][1], bb + 25600 + boff);
            }
#pragma unroll
            for (int nt = 0; nt < 4; nt++) {
                mma16816(acc[nt], aH, bH[nt]);
                mma16816(acc[nt], aH, bL[nt]);
                mma16816(acc[nt], aM, bH[nt]);
            }
        }
        __syncthreads();
    }

    {
        int r = m0 + wm * 16 + g;
#pragma unroll
        for (int nt = 0; nt < 4; nt++) {
            int c = n0 + wn * 32 + nt * 8 + tg * 2;
            if (c < VOCAB)     out[(size_t)r * VOCAB + c]           = acc[nt][0];
            if (c + 1 < VOCAB) out[(size_t)r * VOCAB + c + 1]       = acc[nt][1];
            if (c < VOCAB)     out[(size_t)(r + 8) * VOCAB + c]     = acc[nt][2];
            if (c + 1 < VOCAB) out[(size_t)(r + 8) * VOCAB + c + 1] = acc[nt][3];
        }
    }
}

// ---------------------------------------------------------------- launch

extern "C" void kernel_launch(void* const* d_in, const int* in_sizes, int n_in,
                              void* d_out, int out_size) {
    const int*   ids = (const int*)d_in[0];
    const float* emb = (const float*)d_in[1];
    const float* wp  = (const float*)d_in[2];
    const float* w0  = (const float*)d_in[3];
    const float* s0  = (const float*)d_in[4];
    const float* w1  = (const float*)d_in[5];
    const float* s1  = (const float*)d_in[6];
    const float* rw  = (const float*)d_in[7];
    const float* rb  = (const float*)d_in[8];
    float* out = (float*)d_out;

    static bool attr_set = false;
    if (!attr_set) {
        cudaFuncSetAttribute(layer_gemm_kernel, cudaFuncAttributeMaxDynamicSharedMemorySize,
                             L_NBUF * L_BUF + 8192);
        cudaFuncSetAttribute(final_gemm_kernel, cudaFuncAttributeMaxDynamicSharedMemorySize,
                             F_NBUF * F_BUF);
        attr_set = true;
    }

    embed_kernel<<<NTOK, 256>>>(ids, emb);
    conv_w_kernel<<<(NLAYER * D * D / 4) / 256, 256>>>(w0, w1);

    for (int l = 0; l < NLAYER; l++) {
        int par = l & 1;
        router_kernel<<<NTOK / 8, 256>>>(par, rw + (size_t)l * D, rb + l,
                                         out + (size_t)NTOK * VOCAB + (size_t)l * NTOK);
        layer_gemm_kernel<<<dim3(D / BN, NTOK / BM_L), 256, L_NBUF * L_BUF + 8192>>>(
            par, l, s0 + (size_t)l * D * NBLK, s1 + (size_t)l * D * NBLK);
        if (l == 0)
            conv_wp_kernel<<<((size_t)VPAD * D / 4) / 256, 256>>>(wp);
    }

    final_gemm_kernel<<<dim3(NTOK / BM, VPAD / BN), 512, F_NBUF * F_BUF>>>(out);
}

// round 13
// speedup vs baseline: 1.1747x; 1.1747x over previous
#include <cuda_runtime.h>
#include <cuda_bf16.h>
#include <cstdint>

#define D      1024
#define NTOK   2048
#define VOCAB  50257
#define VPAD   50304
#define NLAYER 12
#define NBLK   16

#define BM 128
#define BM_L 64
#define BN 64
#define BK 32

#define L_ARR 5120
#define L_BUF 25600          // AH AM AL B0 B1 (64x40 bf16 each)
#define L_SMEM (2 * L_BUF + 8192)   // 2 buffers + scale stage = 59392 B -> 3 CTAs/SM
#define F_BUF 30720          // AH AM (128x40) + BH BL (64x40)
#define F_NBUF 3

// ---------------- scratch ----------------
__device__ float g_xbuf[2][NTOK * D];
__device__ float g_p[NTOK];
__device__ __nv_bfloat16 g_xs[2][3][NTOK * D];
__device__ __nv_bfloat16 g_wb[(size_t)NLAYER * 2 * D * D];
__device__ __nv_bfloat16 g_wp2[2][(size_t)VPAD * D];

// ---------------------------------------------------------------- helpers

__device__ __forceinline__ void mma16816(float* c, const uint32_t* a, const uint32_t* b) {
    asm volatile(
        "mma.sync.aligned.m16n8k16.row.col.f32.bf16.bf16.f32 "
        "{%0,%1,%2,%3}, {%4,%5,%6,%7}, {%8,%9}, {%0,%1,%2,%3};"
        : "+f"(c[0]), "+f"(c[1]), "+f"(c[2]), "+f"(c[3])
        : "r"(a[0]), "r"(a[1]), "r"(a[2]), "r"(a[3]), "r"(b[0]), "r"(b[1]));
}

__device__ __forceinline__ void mma16816_z(float* c, const uint32_t* a, const uint32_t* b) {
    asm volatile(
        "mma.sync.aligned.m16n8k16.row.col.f32.bf16.bf16.f32 "
        "{%0,%1,%2,%3}, {%4,%5,%6,%7}, {%8,%9}, {%10,%11,%12,%13};"
        : "=f"(c[0]), "=f"(c[1]), "=f"(c[2]), "=f"(c[3])
        : "r"(a[0]), "r"(a[1]), "r"(a[2]), "r"(a[3]), "r"(b[0]), "r"(b[1]),
          "f"(0.f), "f"(0.f), "f"(0.f), "f"(0.f));
}

__device__ __forceinline__ uint32_t smem_u32(const void* p) {
    uint32_t a;
    asm("{ .reg .u64 t; cvta.to.shared.u64 t, %1; cvt.u32.u64 %0, t; }" : "=r"(a) : "l"(p));
    return a;
}

__device__ __forceinline__ void ldsm_x4(uint32_t& r0, uint32_t& r1, uint32_t& r2, uint32_t& r3,
                                        uint32_t addr) {
    asm volatile("ldmatrix.sync.aligned.m8n8.x4.shared.b16 {%0,%1,%2,%3}, [%4];"
                 : "=r"(r0), "=r"(r1), "=r"(r2), "=r"(r3) : "r"(addr));
}

__device__ __forceinline__ void cpa16(uint32_t smaddr, const void* g) {
    asm volatile("cp.async.ca.shared.global [%0], [%1], 16;" :: "r"(smaddr), "l"(g) : "memory");
}
#define CP_COMMIT() asm volatile("cp.async.commit_group;" ::: "memory")
#define CP_WAIT1()  asm volatile("cp.async.wait_group 1;" ::: "memory")
#define CP_WAIT0()  asm volatile("cp.async.wait_group 0;" ::: "memory")

__device__ __forceinline__ void split3(float x, __nv_bfloat16& h, __nv_bfloat16& m, __nv_bfloat16& l) {
    h = __float2bfloat16(x);
    float r1 = x - __bfloat162float(h);
    m = __float2bfloat16(r1);
    float r2 = r1 - __bfloat162float(m);
    l = __float2bfloat16(r2);
}

__device__ __forceinline__ void split2(float x, __nv_bfloat16& h, __nv_bfloat16& l) {
    h = __float2bfloat16(x);
    l = __float2bfloat16(x - __bfloat162float(h));
}

__device__ __forceinline__ uint32_t pack_bf2(__nv_bfloat16 a, __nv_bfloat16 b) {
    __nv_bfloat162 t(a, b);
    return *reinterpret_cast<uint32_t*>(&t);
}

// ---------------------------------------------------------------- pre-convert

__global__ void conv_w_kernel(const float* __restrict__ w0, const float* __restrict__ w1) {
    size_t t = (size_t)blockIdx.x * 256 + threadIdx.x;
    size_t e = t * 4;
    int l = (int)(e >> 20);
    size_t off = e & 1048575;
    float4 v0 = *reinterpret_cast<const float4*>(w0 + e);
    float4 v1 = *reinterpret_cast<const float4*>(w1 + e);
    uint2 p0, p1;
    p0.x = pack_bf2(__float2bfloat16(v0.x), __float2bfloat16(v0.y));
    p0.y = pack_bf2(__float2bfloat16(v0.z), __float2bfloat16(v0.w));
    p1.x = pack_bf2(__float2bfloat16(v1.x), __float2bfloat16(v1.y));
    p1.y = pack_bf2(__float2bfloat16(v1.z), __float2bfloat16(v1.w));
    __nv_bfloat16* d0 = g_wb + (size_t)l * 2097152 + off;
    *reinterpret_cast<uint2*>(d0) = p0;
    *reinterpret_cast<uint2*>(d0 + 1048576) = p1;
}

__global__ void conv_wp_kernel(const float* __restrict__ wp) {
    size_t t = (size_t)blockIdx.x * 256 + threadIdx.x;
    size_t e = t * 4;
    size_t row = e >> 10;
    float4 v = make_float4(0.f, 0.f, 0.f, 0.f);
    if (row < VOCAB) v = *reinterpret_cast<const float4*>(wp + e);
    __nv_bfloat16 h0, l0, h1, l1, h2, l2, h3, l3;
    split2(v.x, h0, l0); split2(v.y, h1, l1); split2(v.z, h2, l2); split2(v.w, h3, l3);
    uint2 ph, pl;
    ph.x = pack_bf2(h0, h1); ph.y = pack_bf2(h2, h3);
    pl.x = pack_bf2(l0, l1); pl.y = pack_bf2(l2, l3);
    *reinterpret_cast<uint2*>(&g_wp2[0][e]) = ph;
    *reinterpret_cast<uint2*>(&g_wp2[1][e]) = pl;
}

// ---------------------------------------------------------------- embed / router

__global__ void embed_kernel(const int* __restrict__ ids, const float* __restrict__ emb) {
    int n = blockIdx.x;
    int tid = threadIdx.x;
    int id = ids[n];
    float4 v = reinterpret_cast<const float4*>(emb + (size_t)id * D)[tid];
    reinterpret_cast<float4*>(&g_xbuf[0][(size_t)n * D])[tid] = v;
    __nv_bfloat16 h0, m0, l0, h1, m1, l1, h2, m2, l2, h3, m3, l3;
    split3(v.x, h0, m0, l0); split3(v.y, h1, m1, l1);
    split3(v.z, h2, m2, l2); split3(v.w, h3, m3, l3);
    size_t e = (size_t)n * D + tid * 4;
    uint2 p;
    p.x = pack_bf2(h0, h1); p.y = pack_bf2(h2, h3);
    *reinterpret_cast<uint2*>(&g_xs[0][0][e]) = p;
    p.x = pack_bf2(m0, m1); p.y = pack_bf2(m2, m3);
    *reinterpret_cast<uint2*>(&g_xs[0][1][e]) = p;
    p.x = pack_bf2(l0, l1); p.y = pack_bf2(l2, l3);
    *reinterpret_cast<uint2*>(&g_xs[0][2][e]) = p;
}

__global__ __launch_bounds__(256) void router_kernel(
    int par, const float* __restrict__ rw,
    const float* __restrict__ rb, float* __restrict__ probs_out)
{
    int warp = threadIdx.x >> 5, lane = threadIdx.x & 31;
    int n = blockIdx.x * 8 + warp;
    const float4* x = reinterpret_cast<const float4*>(&g_xbuf[par][(size_t)n * D]);
    const float4* w = reinterpret_cast<const float4*>(rw);
    float s = 0.f;
#pragma unroll
    for (int i = 0; i < 8; i++) {
        float4 xv = x[i * 32 + lane];
        float4 wv = __ldg(&w[i * 32 + lane]);
        s += xv.x * wv.x + xv.y * wv.y + xv.z * wv.z + xv.w * wv.w;
    }
#pragma unroll
    for (int off = 16; off > 0; off >>= 1)
        s += __shfl_xor_sync(0xFFFFFFFF, s, off);
    if (lane == 0) {
        float p = 1.f / (1.f + expf(-(s + rb[0])));
        g_p[n] = p;
        probs_out[n] = p;
    }
}

// ---------------------------------------------------------------- per-layer dual GEMM
// 80-reg inner loop (single c, fold-per-ks, smem scales), proper 1-ahead
// double buffer (issue -> WAIT1 -> sync -> compute -> sync), 3 CTAs/SM.

__global__ __launch_bounds__(256, 3) void layer_gemm_kernel(
    int par, int l,
    const float* __restrict__ s0, const float* __restrict__ s1)
{
    extern __shared__ char sm[];
    const float* x_in  = g_xbuf[par];
    float*       x_out = g_xbuf[par ^ 1];
    const __nv_bfloat16* xsH = g_xs[par][0];
    const __nv_bfloat16* xsM = g_xs[par][1];
    const __nv_bfloat16* xsL = g_xs[par][2];
    const __nv_bfloat16* wb = g_wb + (size_t)l * 2097152;

    uint32_t smb = smem_u32(sm);
    float* ss0 = reinterpret_cast<float*>(sm + 2 * L_BUF);   // [16][64]
    float* ss1 = ss0 + 1024;
    int tid = threadIdx.x;
    int lane = tid & 31, warp = tid >> 5;
    int wm = warp >> 1, wn = warp & 1;
    int g = lane >> 2, tg = lane & 3;
    int lrow = lane & 7, sel = lane >> 3;
    int m0 = blockIdx.y * BM_L;
    int n0 = blockIdx.x * BN;
    int rr = tid >> 2, c4 = tid & 3;

    for (int e = tid; e < 1024; e += 256) {
        int kb = e >> 6, col = e & 63;
        ss0[e] = __ldg(&s0[(size_t)(n0 + col) * NBLK + kb]);
        ss1[e] = __ldg(&s1[(size_t)(n0 + col) * NBLK + kb]);
    }

    float p0r = g_p[m0 + wm * 16 + g];
    float p1r = g_p[m0 + wm * 16 + g + 8];

    float acc0T[4][4], acc1T[4][4];
#pragma unroll
    for (int j = 0; j < 4; j++)
#pragma unroll
        for (int q = 0; q < 4; q++) { acc0T[j][q] = 0.f; acc1T[j][q] = 0.f; }

    auto load_tile = [&](int buf, int k0) {
        uint32_t dstb = smb + buf * L_BUF + rr * 80 + c4 * 16;
        size_t asrc = (size_t)(m0 + rr) * D + k0 + c4 * 8;
        size_t bsrc = (size_t)(n0 + rr) * D + k0 + c4 * 8;
        cpa16(dstb,             xsH + asrc);
        cpa16(dstb + 1 * L_ARR, xsM + asrc);
        cpa16(dstb + 2 * L_ARR, xsL + asrc);
        cpa16(dstb + 3 * L_ARR, wb + bsrc);
        cpa16(dstb + 4 * L_ARR, wb + 1048576 + bsrc);
    };

    load_tile(0, 0); CP_COMMIT();

    for (int ktg = 0; ktg < 32; ktg++) {
        int buf = ktg & 1;
        if (ktg + 1 < 32) { load_tile(buf ^ 1, (ktg + 1) * BK); CP_COMMIT(); CP_WAIT1(); }
        else CP_WAIT0();
        __syncthreads();                    // buf data visible to all warps

        int kb = ktg >> 1;
        const float* ssk0 = ss0 + kb * 64;
        const float* ssk1 = ss1 + kb * 64;
        uint32_t bb = smb + buf * L_BUF;

#pragma unroll
        for (int ks = 0; ks < BK; ks += 16) {
            uint32_t aoff = (uint32_t)((wm * 16 + lrow + (sel & 1) * 8) * 80 + (ks + (sel >> 1) * 8) * 2);
            uint32_t aH[4], aM[4], aL[4];
            ldsm_x4(aH[0], aH[1], aH[2], aH[3], bb + aoff);
            ldsm_x4(aM[0], aM[1], aM[2], aM[3], bb + 1 * L_ARR + aoff);
            ldsm_x4(aL[0], aL[1], aL[2], aL[3], bb + 2 * L_ARR + aoff);

            uint32_t b[4][2];
            float c[4][4];
            // ---- branch 0 ----
#pragma unroll
            for (int p2 = 0; p2 < 2; p2++) {
                uint32_t boff = (uint32_t)((wn * 32 + p2 * 16 + lrow + (sel >> 1) * 8) * 80 + (ks + (sel & 1) * 8) * 2);
                ldsm_x4(b[p2*2][0], b[p2*2][1], b[p2*2+1][0], b[p2*2+1][1], bb + 3 * L_ARR + boff);
            }
#pragma unroll
            for (int nt = 0; nt < 4; nt++) {
                mma16816_z(c[nt], aH, b[nt]);
                mma16816(c[nt], aM, b[nt]);
                mma16816(c[nt], aL, b[nt]);
            }
#pragma unroll
            for (int nt = 0; nt < 4; nt++) {
                int cl = wn * 32 + nt * 8 + tg * 2;
                float2 sv = *reinterpret_cast<const float2*>(ssk0 + cl);
                acc0T[nt][0] += sv.x * c[nt][0]; acc0T[nt][1] += sv.y * c[nt][1];
                acc0T[nt][2] += sv.x * c[nt][2]; acc0T[nt][3] += sv.y * c[nt][3];
            }
            // ---- branch 1 ----
#pragma unroll
            for (int p2 = 0; p2 < 2; p2++) {
                uint32_t boff = (uint32_t)((wn * 32 + p2 * 16 + lrow + (sel >> 1) * 8) * 80 + (ks + (sel & 1) * 8) * 2);
                ldsm_x4(b[p2*2][0], b[p2*2][1], b[p2*2+1][0], b[p2*2+1][1], bb + 4 * L_ARR + boff);
            }
#pragma unroll
            for (int nt = 0; nt < 4; nt++) {
                mma16816_z(c[nt], aH, b[nt]);
                mma16816(c[nt], aM, b[nt]);
                mma16816(c[nt], aL, b[nt]);
            }
#pragma unroll
            for (int nt = 0; nt < 4; nt++) {
                int cl = wn * 32 + nt * 8 + tg * 2;
                float2 sv = *reinterpret_cast<const float2*>(ssk1 + cl);
                acc1T[nt][0] += sv.x * c[nt][0]; acc1T[nt][1] += sv.y * c[nt][1];
                acc1T[nt][2] += sv.x * c[nt][2]; acc1T[nt][3] += sv.y * c[nt][3];
            }
        }
        __syncthreads();                    // all reads of buf done before next overwrite
    }

    // epilogue
    {
        __nv_bfloat16* oH = g_xs[par ^ 1][0];
        __nv_bfloat16* oM = g_xs[par ^ 1][1];
        __nv_bfloat16* oL = g_xs[par ^ 1][2];
        int r = m0 + wm * 16 + g;
        float w0a = 1.f - p0r, w0b = 1.f - p1r;
#pragma unroll
        for (int nt = 0; nt < 4; nt++) {
            int cidx = n0 + wn * 32 + nt * 8 + tg * 2;
            size_t idx[4] = { (size_t)r * D + cidx, (size_t)r * D + cidx + 1,
                              (size_t)(r + 8) * D + cidx, (size_t)(r + 8) * D + cidx + 1 };
            float vals[4];
            vals[0] = x_in[idx[0]] + w0a * acc0T[nt][0] + p0r * acc1T[nt][0];
            vals[1] = x_in[idx[1]] + w0a * acc0T[nt][1] + p0r * acc1T[nt][1];
            vals[2] = x_in[idx[2]] + w0b * acc0T[nt][2] + p1r * acc1T[nt][2];
            vals[3] = x_in[idx[3]] + w0b * acc0T[nt][3] + p1r * acc1T[nt][3];
#pragma unroll
            for (int q = 0; q < 4; q++) {
                x_out[idx[q]] = vals[q];
                __nv_bfloat16 h, m, l2;
                split3(vals[q], h, m, l2);
                oH[idx[q]] = h; oM[idx[q]] = m; oL[idx[q]] = l2;
            }
        }
    }
}

// ---------------------------------------------------------------- output projection
// R11 version verbatim: 256 threads, BM128xBN64, 3 products, 3-buffer 1-ahead.

__global__ __launch_bounds__(256, 2) void final_gemm_kernel(float* __restrict__ out) {
    extern __shared__ char sm[];
    const __nv_bfloat16* xH = g_xs[0][0];
    const __nv_bfloat16* xM = g_xs[0][1];
    const __nv_bfloat16* wH = g_wp2[0];
    const __nv_bfloat16* wL = g_wp2[1];

    uint32_t smb = smem_u32(sm);
    int tid = threadIdx.x;
    int lane = tid & 31, warp = tid >> 5;
    int wm = warp >> 1, wn = warp & 1;
    int g = lane >> 2, tg = lane & 3;
    int lrow = lane & 7, sel = lane >> 3;
    int m0 = blockIdx.x * BM;
    int n0 = blockIdx.y * BN;
    int rr = tid >> 2, c4 = tid & 3;

    float acc[2][4][4];
#pragma unroll
    for (int i = 0; i < 2; i++)
#pragma unroll
        for (int j = 0; j < 4; j++)
#pragma unroll
            for (int q = 0; q < 4; q++) acc[i][j][q] = 0.f;

    auto load_tile = [&](int buf, int k0) {
        uint32_t dstb = smb + buf * F_BUF + rr * 80 + c4 * 16;
        size_t a0 = (size_t)(m0 + rr) * D + k0 + c4 * 8;
        size_t a1 = (size_t)(m0 + rr + 64) * D + k0 + c4 * 8;
        size_t bsrc = (size_t)(n0 + rr) * D + k0 + c4 * 8;
        cpa16(dstb,                 xH + a0);
        cpa16(dstb + 64 * 80,       xH + a1);
        cpa16(dstb + 10240,         xM + a0);
        cpa16(dstb + 10240 + 64*80, xM + a1);
        cpa16(dstb + 20480,         wH + bsrc);
        cpa16(dstb + 25600,         wL + bsrc);
    };

    load_tile(0, 0); CP_COMMIT();

    int bufc = 0;
    for (int kt = 0; kt < 32; kt++) {
        if (kt + 1 < 32) {
            int nb = bufc + 1; if (nb == F_NBUF) nb = 0;
            load_tile(nb, (kt + 1) * BK); CP_COMMIT();
            CP_WAIT1();
        } else CP_WAIT0();
        __syncthreads();

        uint32_t bb = smb + bufc * F_BUF;
#pragma unroll
        for (int ks = 0; ks < BK; ks += 16) {
            uint32_t aH[2][4], aM[2][4];
#pragma unroll
            for (int mt = 0; mt < 2; mt++) {
                uint32_t aoff = (uint32_t)((wm * 32 + mt * 16 + lrow + (sel & 1) * 8) * 80 + (ks + (sel >> 1) * 8) * 2);
                ldsm_x4(aH[mt][0], aH[mt][1], aH[mt][2], aH[mt][3], bb + aoff);
                ldsm_x4(aM[mt][0], aM[mt][1], aM[mt][2], aM[mt][3], bb + 10240 + aoff);
            }
            uint32_t bH[4][2], bL[4][2];
#pragma unroll
            for (int p2 = 0; p2 < 2; p2++) {
                uint32_t boff = (uint32_t)((wn * 32 + p2 * 16 + lrow + (sel >> 1) * 8) * 80 + (ks + (sel & 1) * 8) * 2);
                ldsm_x4(bH[p2*2][0], bH[p2*2][1], bH[p2*2+1][0], bH[p2*2+1][1], bb + 20480 + boff);
                ldsm_x4(bL[p2*2][0], bL[p2*2][1], bL[p2*2+1][0], bL[p2*2+1][1], bb + 25600 + boff);
            }
#pragma unroll
            for (int mt = 0; mt < 2; mt++)
#pragma unroll
                for (int nt = 0; nt < 4; nt++) {
                    mma16816(acc[mt][nt], aH[mt], bH[nt]);
                    mma16816(acc[mt][nt], aH[mt], bL[nt]);
                    mma16816(acc[mt][nt], aM[mt], bH[nt]);
                }
        }
        bufc++; if (bufc == F_NBUF) bufc = 0;
    }

#pragma unroll
    for (int mt = 0; mt < 2; mt++) {
        int r = m0 + wm * 32 + mt * 16 + g;
#pragma unroll
        for (int nt = 0; nt < 4; nt++) {
            int c = n0 + wn * 32 + nt * 8 + tg * 2;
            if (c < VOCAB)     out[(size_t)r * VOCAB + c]           = acc[mt][nt][0];
            if (c + 1 < VOCAB) out[(size_t)r * VOCAB + c + 1]       = acc[mt][nt][1];
            if (c < VOCAB)     out[(size_t)(r + 8) * VOCAB + c]     = acc[mt][nt][2];
            if (c + 1 < VOCAB) out[(size_t)(r + 8) * VOCAB + c + 1] = acc[mt][nt][3];
        }
    }
}

// ---------------------------------------------------------------- launch

extern "C" void kernel_launch(void* const* d_in, const int* in_sizes, int n_in,
                              void* d_out, int out_size) {
    const int*   ids = (const int*)d_in[0];
    const float* emb = (const float*)d_in[1];
    const float* wp  = (const float*)d_in[2];
    const float* w0  = (const float*)d_in[3];
    const float* s0  = (const float*)d_in[4];
    const float* w1  = (const float*)d_in[5];
    const float* s1  = (const float*)d_in[6];
    const float* rw  = (const float*)d_in[7];
    const float* rb  = (const float*)d_in[8];
    float* out = (float*)d_out;

    static bool attr_set = false;
    if (!attr_set) {
        cudaFuncSetAttribute(layer_gemm_kernel, cudaFuncAttributeMaxDynamicSharedMemorySize, L_SMEM);
        cudaFuncSetAttribute(final_gemm_kernel, cudaFuncAttributeMaxDynamicSharedMemorySize,
                             F_NBUF * F_BUF);
        attr_set = true;
    }

    embed_kernel<<<NTOK, 256>>>(ids, emb);
    conv_w_kernel<<<(NLAYER * D * D / 4) / 256, 256>>>(w0, w1);

    for (int l = 0; l < NLAYER; l++) {
        int par = l & 1;
        router_kernel<<<NTOK / 8, 256>>>(par, rw + (size_t)l * D, rb + l,
                                         out + (size_t)NTOK * VOCAB + (size_t)l * NTOK);
        layer_gemm_kernel<<<dim3(D / BN, NTOK / BM_L), 256, L_SMEM>>>(
            par, l, s0 + (size_t)l * D * NBLK, s1 + (size_t)l * D * NBLK);
        if (l == 0)
            conv_wp_kernel<<<((size_t)VPAD * D / 4) / 256, 256>>>(wp);
    }

    final_gemm_kernel<<<dim3(NTOK / BM, VPAD / BN), 256, F_NBUF * F_BUF>>>(out);
}